// round 2
// baseline (speedup 1.0000x reference)
#include <cuda_runtime.h>

// Problem constants
#define Bn  16
#define Cn  32
#define Nn  128
#define Tn  12
#define COn 64
#define NT  (Nn * Tn)          // 1536 floats per (b,i,j) row of A
#define NT4 (NT / 4)           // 384 float4
#define NSLICE (Bn * Cn)       // 512 (b,i) slices

// Dummy dynamic smem pad to force 1 CTA/SM (228KB/SM; 12KB static + 110KB pad -> no room for 2)
#define PROP_PAD (110 * 1024)

// Scratch: h = concat([x1, x2], channel axis) -> [B][2C][N*T] = 6.3 MB
__device__ float g_h[(size_t)Bn * 2 * Cn * NT];

// ---------------------------------------------------------------------------
// Kernel 1: fused order-1 + order-2 propagation, PERSISTENT, 1 CTA/SM.
// CTA processes slices bc = blockIdx.x, += gridDim.x. With 1 CTA/SM, the
// concurrent A working set is ~148 x 786KB = 116MB <= L2 (126MB), so the
// pass-2 re-read of the slice hits L2 instead of HBM.
// Thread t owns elements [4t,4t+4) of the 1536-wide (k,l) plane; since 4|12
// each float4 has fixed k and l0 in {0,4,8} -> multiplier is one LDS.128.
// ---------------------------------------------------------------------------
extern __shared__ char s_pad[];   // occupancy limiter (never accessed)

__global__ __launch_bounds__(NT4) void prop_kernel(const float* __restrict__ x,
                                                   const float* __restrict__ A) {
    __shared__ float4 xs[NT4];    // x[b,i,:,:]  as [j*3 + l0/4]
    __shared__ float4 x1s[NT4];   // x1[b,i,:,:] same layout

    const int t  = threadIdx.x;   // 0..383
    const int lq = t % 3;         // l0 / 4

    for (int bc = blockIdx.x; bc < NSLICE; bc += gridDim.x) {
        const float4* __restrict__ xp = (const float4*)(x + (size_t)bc * NT);
        const float4* __restrict__ Ap = (const float4*)(A + (size_t)bc * Nn * NT);

        xs[t] = xp[t];
        __syncthreads();   // also serves as the end-of-previous-iteration barrier

        // ---- Pass 1: x1[k,l] = sum_j x[j,l] * A[j,k,l]  (HBM stream, fills L2)
        float4 acc1 = make_float4(0.f, 0.f, 0.f, 0.f);
#pragma unroll 8
        for (int j = 0; j < Nn; ++j) {
            float4 a  = Ap[j * NT4 + t];
            float4 xv = xs[j * 3 + lq];
            acc1.x = fmaf(a.x, xv.x, acc1.x);
            acc1.y = fmaf(a.y, xv.y, acc1.y);
            acc1.z = fmaf(a.z, xv.z, acc1.z);
            acc1.w = fmaf(a.w, xv.w, acc1.w);
        }
        x1s[t] = acc1;
        __syncthreads();

        // ---- Pass 2: x2[k,l] = sum_j x1[j,l] * A[j,k,l]  (L2 re-read, last-use)
        float4 acc2 = make_float4(0.f, 0.f, 0.f, 0.f);
#pragma unroll 8
        for (int j = 0; j < Nn; ++j) {
            float4 a  = __ldlu(&Ap[j * NT4 + t]);
            float4 xv = x1s[j * 3 + lq];
            acc2.x = fmaf(a.x, xv.x, acc2.x);
            acc2.y = fmaf(a.y, xv.y, acc2.y);
            acc2.z = fmaf(a.z, xv.z, acc2.z);
            acc2.w = fmaf(a.w, xv.w, acc2.w);
        }

        // ---- h[b, i, :] = x1 ; h[b, C+i, :] = x2
        const int b = bc / Cn;
        const int i = bc % Cn;
        ((float4*)(g_h + ((size_t)b * 2 * Cn + i) * NT))[t]      = acc1;
        ((float4*)(g_h + ((size_t)b * 2 * Cn + Cn + i) * NT))[t] = acc2;
    }
}

// ---------------------------------------------------------------------------
// Kernel 2: 1x1 conv channel mix as a smem-tiled GEMM.
// out[b,o,col] = sum_c W[o,c] * h[b,c,col] + bias[o]
// Block: 256 threads, tile = 64 outs x 64 cols of one batch.
// Thread (oq=t/16, colq=t%16) computes 4 outs x 4 cols (4 float4 accs).
// Grid = B * (NT/64) = 16*24 = 384 blocks -> ~2.6 blocks/SM.
// ---------------------------------------------------------------------------
#define MIX_COLS 64
#define MIX_NCB  (NT / MIX_COLS)   // 24

__global__ __launch_bounds__(256) void mix_kernel(const float* __restrict__ W,
                                                  const float* __restrict__ bias,
                                                  float* __restrict__ out) {
    __shared__ float4 hs[(2 * Cn) * (MIX_COLS / 4)];   // [c][16] float4 = 16 KB
    __shared__ float  Ws[COn * 2 * Cn];                // [o][c] = 16 KB
    __shared__ float  bs[COn];

    const int t    = threadIdx.x;
    const int b    = blockIdx.x / MIX_NCB;
    const int col0 = (blockIdx.x % MIX_NCB) * MIX_COLS;
    const int colq = t & 15;       // float4 column within tile
    const int oq   = t >> 4;       // 0..15, owns outs [4oq, 4oq+4)

    // Load W [64x64] and bias
    {
        float4*       Wd = (float4*)Ws;
        const float4* W4 = (const float4*)W;
#pragma unroll
        for (int s = 0; s < 4; ++s) Wd[t + 256 * s] = W4[t + 256 * s];
        if (t < COn) bs[t] = bias[t];
    }
    // Load h tile: 64 channels x 16 float4, 4 per thread (coalesced per channel row)
    {
        const float* hb = g_h + (size_t)b * 2 * Cn * NT + col0;
#pragma unroll
        for (int s = 0; s < 4; ++s) {
            int idx = t + 256 * s;             // 0..1023
            int c   = idx >> 4;
            int v   = idx & 15;
            hs[idx] = ((const float4*)(hb + (size_t)c * NT))[v];
        }
    }
    __syncthreads();

    float4 acc0 = make_float4(bs[4 * oq + 0], bs[4 * oq + 0], bs[4 * oq + 0], bs[4 * oq + 0]);
    float4 acc1 = make_float4(bs[4 * oq + 1], bs[4 * oq + 1], bs[4 * oq + 1], bs[4 * oq + 1]);
    float4 acc2 = make_float4(bs[4 * oq + 2], bs[4 * oq + 2], bs[4 * oq + 2], bs[4 * oq + 2]);
    float4 acc3 = make_float4(bs[4 * oq + 3], bs[4 * oq + 3], bs[4 * oq + 3], bs[4 * oq + 3]);

#pragma unroll 8
    for (int c = 0; c < 2 * Cn; ++c) {
        float4 hv = hs[c * 16 + colq];
        float  w0 = Ws[(4 * oq + 0) * 2 * Cn + c];
        float  w1 = Ws[(4 * oq + 1) * 2 * Cn + c];
        float  w2 = Ws[(4 * oq + 2) * 2 * Cn + c];
        float  w3 = Ws[(4 * oq + 3) * 2 * Cn + c];
        acc0.x = fmaf(w0, hv.x, acc0.x); acc0.y = fmaf(w0, hv.y, acc0.y);
        acc0.z = fmaf(w0, hv.z, acc0.z); acc0.w = fmaf(w0, hv.w, acc0.w);
        acc1.x = fmaf(w1, hv.x, acc1.x); acc1.y = fmaf(w1, hv.y, acc1.y);
        acc1.z = fmaf(w1, hv.z, acc1.z); acc1.w = fmaf(w1, hv.w, acc1.w);
        acc2.x = fmaf(w2, hv.x, acc2.x); acc2.y = fmaf(w2, hv.y, acc2.y);
        acc2.z = fmaf(w2, hv.z, acc2.z); acc2.w = fmaf(w2, hv.w, acc2.w);
        acc3.x = fmaf(w3, hv.x, acc3.x); acc3.y = fmaf(w3, hv.y, acc3.y);
        acc3.z = fmaf(w3, hv.z, acc3.z); acc3.w = fmaf(w3, hv.w, acc3.w);
    }

    float* ob = out + (size_t)b * COn * NT + col0;
    ((float4*)(ob + (size_t)(4 * oq + 0) * NT))[colq] = acc0;
    ((float4*)(ob + (size_t)(4 * oq + 1) * NT))[colq] = acc1;
    ((float4*)(ob + (size_t)(4 * oq + 2) * NT))[colq] = acc2;
    ((float4*)(ob + (size_t)(4 * oq + 3) * NT))[colq] = acc3;
}

// ---------------------------------------------------------------------------
extern "C" void kernel_launch(void* const* d_in, const int* in_sizes, int n_in,
                              void* d_out, int out_size) {
    const float* x    = (const float*)d_in[0];   // [B,C,N,T]
    const float* A    = (const float*)d_in[1];   // [B,C,N,N,T]
    const float* W    = (const float*)d_in[2];   // [C_OUT, 2C]
    const float* bias = (const float*)d_in[3];   // [C_OUT]
    float* out = (float*)d_out;                  // [B,C_OUT,N,T]

    int dev = 0, nsm = 148;
    cudaGetDevice(&dev);
    cudaDeviceGetAttribute(&nsm, cudaDevAttrMultiProcessorCount, dev);
    cudaFuncSetAttribute(prop_kernel, cudaFuncAttributeMaxDynamicSharedMemorySize, PROP_PAD);

    prop_kernel<<<nsm, NT4, PROP_PAD>>>(x, A);
    mix_kernel<<<Bn * MIX_NCB, 256>>>(W, bias, out);
}

// round 3
// speedup vs baseline: 2.0843x; 2.0843x over previous
#include <cuda_runtime.h>

// Problem constants
#define Bn  16
#define Cn  32
#define Nn  128
#define Tn  12
#define COn 64
#define NT  (Nn * Tn)          // 1536 floats per (b,i,j) row of A
#define NT4 (NT / 4)           // 384 float4
#define NSLICE (Bn * Cn)       // 512 (b,i) slices

// prop config: 128 persistent CTAs (1/SM via smem pad), 768 threads =
// 4 groups x 192; each group streams 32 of the 128 j-rows.
#define PROP_CTAS    128
#define PROP_THREADS 768
#define NGRP 4
#define GSZ  192
#define JPG  (Nn / NGRP)       // 32
#define PROP_PAD (150 * 1024)  // dummy dynamic smem: 36.9KB static + 150KB -> 1 CTA/SM

// Scratch: h = concat([x1, x2], channel axis) -> [B][2C][N*T] = 6.3 MB
__device__ float g_h[(size_t)Bn * 2 * Cn * NT];

extern __shared__ char s_pad[];   // occupancy limiter (never accessed)

__device__ __forceinline__ void fma4(float4& acc, const float4 a, const float4 v) {
    acc.x = fmaf(a.x, v.x, acc.x);
    acc.y = fmaf(a.y, v.y, acc.y);
    acc.z = fmaf(a.z, v.z, acc.z);
    acc.w = fmaf(a.w, v.w, acc.w);
}
__device__ __forceinline__ float4 add4(const float4 a, const float4 b) {
    return make_float4(a.x + b.x, a.y + b.y, a.z + b.z, a.w + b.w);
}

// ---------------------------------------------------------------------------
// Kernel 1: fused order-1 + order-2 propagation. Persistent, 1 CTA/SM,
// 24 warps/SM. Pass 1 streams the slice from HBM (fills L2); pass 2 re-reads
// it from L2 (last-use). 4-way j-split with smem partial reduction keeps
// warp count high while per-SM footprint stays at one 786KB slice.
// Plane index v in [0,384): k = v/3, l0 = 4*(v%3); since GSZ % 3 == 0, a
// thread's two owned float4s (v=ti, v=ti+192) share lq = ti%3 -> one LDS
// feeds both FMAs.
// ---------------------------------------------------------------------------
__global__ __launch_bounds__(PROP_THREADS, 1)
void prop_kernel(const float* __restrict__ x, const float* __restrict__ A) {
    __shared__ float4 part[NGRP][NT4];   // 24 KB partial sums
    __shared__ float4 xs[NT4];           // x slice,  [j*3 + lq]
    __shared__ float4 x1s[NT4];          // x1 slice, same layout

    const int t  = threadIdx.x;
    const int g  = t / GSZ;
    const int ti = t - g * GSZ;          // 0..191
    const int lq = ti % 3;
    const int j0 = g * JPG;

    for (int bc = blockIdx.x; bc < NSLICE; bc += PROP_CTAS) {
        const float4* __restrict__ xp = (const float4*)(x + (size_t)bc * NT);
        const float4* __restrict__ Ap = (const float4*)(A + (size_t)bc * Nn * NT);

        if (t < NT4) xs[t] = xp[t];
        __syncthreads();                            // (A) xs ready, part free

        // ---- Pass 1: partial x1 over this group's j-range (HBM stream)
        float4 acc0 = make_float4(0.f, 0.f, 0.f, 0.f);
        float4 acc1 = make_float4(0.f, 0.f, 0.f, 0.f);
        {
            const float4* __restrict__ ap = Ap + (size_t)j0 * NT4;
#pragma unroll 4
            for (int jj = 0; jj < JPG; ++jj) {
                float4 a0 = ap[jj * NT4 + ti];
                float4 a1 = ap[jj * NT4 + ti + GSZ];
                float4 xv = xs[(j0 + jj) * 3 + lq];
                fma4(acc0, a0, xv);
                fma4(acc1, a1, xv);
            }
        }
        part[g][ti]       = acc0;
        part[g][ti + GSZ] = acc1;
        __syncthreads();                            // (B) partials ready

        // ---- Reduce 1: x1 = sum of 4 partials
        float4 r1;
        if (t < NT4) {
            r1 = add4(add4(part[0][t], part[1][t]), add4(part[2][t], part[3][t]));
            x1s[t] = r1;
        }
        __syncthreads();                            // (C) x1s ready, part free

        // ---- Pass 2: partial x2 (L2 re-read, last-use)
        acc0 = make_float4(0.f, 0.f, 0.f, 0.f);
        acc1 = make_float4(0.f, 0.f, 0.f, 0.f);
        {
            const float4* __restrict__ ap = Ap + (size_t)j0 * NT4;
#pragma unroll 4
            for (int jj = 0; jj < JPG; ++jj) {
                float4 a0 = __ldlu(&ap[jj * NT4 + ti]);
                float4 a1 = __ldlu(&ap[jj * NT4 + ti + GSZ]);
                float4 xv = x1s[(j0 + jj) * 3 + lq];
                fma4(acc0, a0, xv);
                fma4(acc1, a1, xv);
            }
        }
        part[g][ti]       = acc0;
        part[g][ti + GSZ] = acc1;
        __syncthreads();                            // (D) partials ready

        // ---- Reduce 2 + write h[b,i,:] = x1, h[b,C+i,:] = x2
        if (t < NT4) {
            float4 r2 = add4(add4(part[0][t], part[1][t]), add4(part[2][t], part[3][t]));
            const int b = bc / Cn;
            const int i = bc % Cn;
            ((float4*)(g_h + ((size_t)b * 2 * Cn + i) * NT))[t]      = r1;
            ((float4*)(g_h + ((size_t)b * 2 * Cn + Cn + i) * NT))[t] = r2;
        }
        // next iteration's barrier (A) orders part reads here vs. pass-1 writes
    }
}

// ---------------------------------------------------------------------------
// Kernel 2: 1x1 conv channel mix as a smem-tiled GEMM (unchanged from R2,
// measured 10.8us). out[b,o,col] = sum_c W[o,c]*h[b,c,col] + bias[o]
// ---------------------------------------------------------------------------
#define MIX_COLS 64
#define MIX_NCB  (NT / MIX_COLS)   // 24

__global__ __launch_bounds__(256) void mix_kernel(const float* __restrict__ W,
                                                  const float* __restrict__ bias,
                                                  float* __restrict__ out) {
    __shared__ float4 hs[(2 * Cn) * (MIX_COLS / 4)];   // 16 KB
    __shared__ float  Ws[COn * 2 * Cn];                // 16 KB
    __shared__ float  bs[COn];

    const int t    = threadIdx.x;
    const int b    = blockIdx.x / MIX_NCB;
    const int col0 = (blockIdx.x % MIX_NCB) * MIX_COLS;
    const int colq = t & 15;
    const int oq   = t >> 4;

    {
        float4*       Wd = (float4*)Ws;
        const float4* W4 = (const float4*)W;
#pragma unroll
        for (int s = 0; s < 4; ++s) Wd[t + 256 * s] = W4[t + 256 * s];
        if (t < COn) bs[t] = bias[t];
    }
    {
        const float* hb = g_h + (size_t)b * 2 * Cn * NT + col0;
#pragma unroll
        for (int s = 0; s < 4; ++s) {
            int idx = t + 256 * s;
            int c   = idx >> 4;
            int v   = idx & 15;
            hs[idx] = ((const float4*)(hb + (size_t)c * NT))[v];
        }
    }
    __syncthreads();

    float4 acc0 = make_float4(bs[4 * oq + 0], bs[4 * oq + 0], bs[4 * oq + 0], bs[4 * oq + 0]);
    float4 acc1 = make_float4(bs[4 * oq + 1], bs[4 * oq + 1], bs[4 * oq + 1], bs[4 * oq + 1]);
    float4 acc2 = make_float4(bs[4 * oq + 2], bs[4 * oq + 2], bs[4 * oq + 2], bs[4 * oq + 2]);
    float4 acc3 = make_float4(bs[4 * oq + 3], bs[4 * oq + 3], bs[4 * oq + 3], bs[4 * oq + 3]);

#pragma unroll 8
    for (int c = 0; c < 2 * Cn; ++c) {
        float4 hv = hs[c * 16 + colq];
        float  w0 = Ws[(4 * oq + 0) * 2 * Cn + c];
        float  w1 = Ws[(4 * oq + 1) * 2 * Cn + c];
        float  w2 = Ws[(4 * oq + 2) * 2 * Cn + c];
        float  w3 = Ws[(4 * oq + 3) * 2 * Cn + c];
        acc0.x = fmaf(w0, hv.x, acc0.x); acc0.y = fmaf(w0, hv.y, acc0.y);
        acc0.z = fmaf(w0, hv.z, acc0.z); acc0.w = fmaf(w0, hv.w, acc0.w);
        acc1.x = fmaf(w1, hv.x, acc1.x); acc1.y = fmaf(w1, hv.y, acc1.y);
        acc1.z = fmaf(w1, hv.z, acc1.z); acc1.w = fmaf(w1, hv.w, acc1.w);
        acc2.x = fmaf(w2, hv.x, acc2.x); acc2.y = fmaf(w2, hv.y, acc2.y);
        acc2.z = fmaf(w2, hv.z, acc2.z); acc2.w = fmaf(w2, hv.w, acc2.w);
        acc3.x = fmaf(w3, hv.x, acc3.x); acc3.y = fmaf(w3, hv.y, acc3.y);
        acc3.z = fmaf(w3, hv.z, acc3.z); acc3.w = fmaf(w3, hv.w, acc3.w);
    }

    float* ob = out + (size_t)b * COn * NT + col0;
    ((float4*)(ob + (size_t)(4 * oq + 0) * NT))[colq] = acc0;
    ((float4*)(ob + (size_t)(4 * oq + 1) * NT))[colq] = acc1;
    ((float4*)(ob + (size_t)(4 * oq + 2) * NT))[colq] = acc2;
    ((float4*)(ob + (size_t)(4 * oq + 3) * NT))[colq] = acc3;
}

// ---------------------------------------------------------------------------
extern "C" void kernel_launch(void* const* d_in, const int* in_sizes, int n_in,
                              void* d_out, int out_size) {
    const float* x    = (const float*)d_in[0];   // [B,C,N,T]
    const float* A    = (const float*)d_in[1];   // [B,C,N,N,T]
    const float* W    = (const float*)d_in[2];   // [C_OUT, 2C]
    const float* bias = (const float*)d_in[3];   // [C_OUT]
    float* out = (float*)d_out;                  // [B,C_OUT,N,T]

    cudaFuncSetAttribute(prop_kernel, cudaFuncAttributeMaxDynamicSharedMemorySize, PROP_PAD);

    prop_kernel<<<PROP_CTAS, PROP_THREADS, PROP_PAD>>>(x, A);
    mix_kernel<<<Bn * MIX_NCB, 256>>>(W, bias, out);
}